// round 2
// baseline (speedup 1.0000x reference)
#include <cuda_runtime.h>

#define D 128
#define TQ 128
#define TK 64
#define NTHREADS 256
#define NGLOBAL 100
#define LPRE 2048

// shared memory layout (in floats)
#define QS_OFF 0
#define KS_OFF (TQ * D)                    // 16384
#define VS_OFF (KS_OFF + TK * D)           // 24576
#define PT_OFF (VS_OFF + TK * D)           // 32768
#define PT_STRIDE (TQ + 1)                 // 129 (odd -> conflict-free scalar writes)
#define SMEM_FLOATS (PT_OFF + TK * PT_STRIDE)

typedef unsigned long long u64;

// ---- packed f32x2 helpers (sm_103a FFMA2 path; ptxas never auto-fuses) ----
__device__ __forceinline__ u64 ffma2(u64 a, u64 b, u64 c) {
    u64 d;
    asm("fma.rn.f32x2 %0, %1, %2, %3;" : "=l"(d) : "l"(a), "l"(b), "l"(c));
    return d;
}
__device__ __forceinline__ u64 fmul2(u64 a, u64 b) {
    u64 d;
    asm("mul.rn.f32x2 %0, %1, %2;" : "=l"(d) : "l"(a), "l"(b));
    return d;
}
__device__ __forceinline__ u64 pack2(float lo, float hi) {
    u64 d;
    asm("mov.b64 %0, {%1, %2};" : "=l"(d) : "f"(lo), "f"(hi));
    return d;
}
__device__ __forceinline__ void unpack2(u64 v, float& lo, float& hi) {
    asm("mov.b64 {%0, %1}, %2;" : "=f"(lo), "=f"(hi) : "l"(v));
}

// fast exp2 for x <= 0 (poly deg-6, rel err ~1e-5). Handles -1e30 sentinel -> ~0.
__device__ __forceinline__ float fexp2(float x) {
    x = fmaxf(x, -126.0f);
    int ni = __float2int_rd(x);
    float f = x - (float)ni;
    float p = 1.54035304e-4f;
    p = fmaf(p, f, 1.33335581e-3f);
    p = fmaf(p, f, 9.61812911e-3f);
    p = fmaf(p, f, 5.55041087e-2f);
    p = fmaf(p, f, 2.40226507e-1f);
    p = fmaf(p, f, 6.93147181e-1f);
    p = fmaf(p, f, 1.0f);
    return __int_as_float(__float_as_int(p) + (ni << 23));
}

__global__ void __launch_bounds__(NTHREADS, 1)
lminf_kernel(const float* __restrict__ Q, const float* __restrict__ K,
             const float* __restrict__ V, float* __restrict__ O, int S) {
    extern __shared__ float sm[];
    float* Qs = sm + QS_OFF;
    float* Ks = sm + KS_OFF;
    float* Vs = sm + VS_OFF;
    float* Pt = sm + PT_OFF;

    const int b  = blockIdx.y;
    const int q0 = blockIdx.x * TQ;
    const int tid = threadIdx.x;
    const int tq = tid >> 4;   // 0..15 : query group (rows tq + 16*m)
    const int tk = tid & 15;   // 0..15 : key group (keys tk + 16*r) / dims (8*tk..8*tk+7)

    const float* Qg = Q + (size_t)b * S * D;
    const float* Kg = K + (size_t)b * S * D;
    const float* Vg = V + (size_t)b * S * D;

    const float QSCALE = 0.0883883476f * 1.44269504089f;  // 1/sqrt(128) * log2(e)
    const float LOG2E  = 1.44269504089f;

    // ---- load Q tile into swizzled smem, pre-scaled ----
    {
        const float4* src = (const float4*)(Qg + (size_t)q0 * D);
        float4* dst = (float4*)Qs;
        #pragma unroll
        for (int it = 0; it < (TQ * 32) / NTHREADS; it++) {
            int idx = tid + it * NTHREADS;
            int row = idx >> 5, d4 = idx & 31;
            float4 val = src[idx];
            val.x *= QSCALE; val.y *= QSCALE; val.z *= QSCALE; val.w *= QSCALE;
            dst[row * 32 + (d4 ^ (row & 7))] = val;
        }
    }

    u64 acc2[8][4];            // packed over d: [m][d-pair group]
    float mrow[8], lrow[8];
    #pragma unroll
    for (int m = 0; m < 8; m++) {
        mrow[m] = -1e30f; lrow[m] = 0.0f;
        #pragma unroll
        for (int c = 0; c < 4; c++) acc2[m][c] = 0ull;
    }

    const int xq = tq & 7;
    const int xk = tk & 7;
    const ulonglong2* Qs8 = (const ulonglong2*)Qs;
    const ulonglong2* Ks8 = (const ulonglong2*)Ks;
    const ulonglong2* Vs8 = (const ulonglong2*)Vs;

    const int kend = q0 + TQ;
    for (int k0 = 0; k0 < kend; k0 += TK) {
        // skip tiles entirely outside global sinks and all local windows of this block
        if (k0 >= NGLOBAL && (k0 + TK) <= (q0 - LPRE + 1)) continue;

        __syncthreads();   // previous tile's PV done reading Vs
        // ---- load K (swizzled) + V (plain) tiles ----
        {
            const float4* ksrc = (const float4*)(Kg + (size_t)k0 * D);
            const float4* vsrc = (const float4*)(Vg + (size_t)k0 * D);
            float4* kdst = (float4*)Ks;
            float4* vdst = (float4*)Vs;
            #pragma unroll
            for (int it = 0; it < (TK * 32) / NTHREADS; it++) {
                int idx = tid + it * NTHREADS;
                int row = idx >> 5, d4 = idx & 31;
                kdst[row * 32 + (d4 ^ (row & 7))] = ksrc[idx];
                vdst[idx] = vsrc[idx];
            }
        }
        __syncthreads();

        // ---- scores: 8q x 4k per thread, packed-d FFMA2, computed in 2 key-halves ----
        float s[8][4];
        #pragma unroll
        for (int half = 0; half < 2; half++) {
            u64 s2[8][2];
            #pragma unroll
            for (int m = 0; m < 8; m++) { s2[m][0] = 0ull; s2[m][1] = 0ull; }

            #pragma unroll 4
            for (int d4 = 0; d4 < 32; d4++) {
                int ck = d4 ^ xk;
                int cq = d4 ^ xq;
                ulonglong2 kvA = Ks8[(tk + 16 * (2 * half + 0)) * 32 + ck];
                ulonglong2 kvB = Ks8[(tk + 16 * (2 * half + 1)) * 32 + ck];
                #pragma unroll
                for (int m = 0; m < 8; m++) {
                    ulonglong2 qv = Qs8[(tq + 16 * m) * 32 + cq];
                    s2[m][0] = ffma2(qv.x, kvA.x, s2[m][0]);
                    s2[m][0] = ffma2(qv.y, kvA.y, s2[m][0]);
                    s2[m][1] = ffma2(qv.x, kvB.x, s2[m][1]);
                    s2[m][1] = ffma2(qv.y, kvB.y, s2[m][1]);
                }
            }
            #pragma unroll
            for (int m = 0; m < 8; m++) {
                float lo, hi;
                unpack2(s2[m][0], lo, hi); s[m][2 * half + 0] = lo + hi;
                unpack2(s2[m][1], lo, hi); s[m][2 * half + 1] = lo + hi;
            }
        }

        // ---- mask + bias + online softmax (log2 domain) ----
        #pragma unroll
        for (int m = 0; m < 8; m++) {
            int i = q0 + tq + 16 * m;
            float val[4];
            float tmax = -1e30f;
            #pragma unroll
            for (int r = 0; r < 4; r++) {
                int j = k0 + tk + 16 * r;
                bool allowed = (j <= i) && ((j < NGLOBAL) || (j >= i - (LPRE - 1)));
                float vv = allowed ? fmaf((float)(j - i), LOG2E, s[m][r]) : -1e30f;
                val[r] = vv;
                tmax = fmaxf(tmax, vv);
            }
            #pragma unroll
            for (int off = 8; off >= 1; off >>= 1)
                tmax = fmaxf(tmax, __shfl_xor_sync(0xffffffffu, tmax, off, 16));

            float mnew  = fmaxf(mrow[m], tmax);
            float scale = fexp2(mrow[m] - mnew);
            float psum = 0.0f;
            #pragma unroll
            for (int r = 0; r < 4; r++) {
                float p = fexp2(val[r] - mnew);
                psum += p;
                Pt[(tk + 16 * r) * PT_STRIDE + (tq + 16 * m)] = p;
            }
            #pragma unroll
            for (int off = 8; off >= 1; off >>= 1)
                psum += __shfl_xor_sync(0xffffffffu, psum, off, 16);

            lrow[m] = lrow[m] * scale + psum;
            mrow[m] = mnew;
            u64 sc2 = pack2(scale, scale);
            #pragma unroll
            for (int c = 0; c < 4; c++) acc2[m][c] = fmul2(acc2[m][c], sc2);
        }
        __syncwarp();   // P exchange is within a half-warp only

        // ---- PV: acc[8q][8d] += P * V, packed-d FFMA2 ----
        #pragma unroll 4
        for (int key = 0; key < TK; key++) {
            ulonglong2 vA = Vs8[key * 32 + tk * 2];
            ulonglong2 vB = Vs8[key * 32 + tk * 2 + 1];
            const float* prow = Pt + key * PT_STRIDE + tq;
            #pragma unroll
            for (int m = 0; m < 8; m++) {
                float p = prow[16 * m];
                u64 pp = pack2(p, p);
                acc2[m][0] = ffma2(pp, vA.x, acc2[m][0]);
                acc2[m][1] = ffma2(pp, vA.y, acc2[m][1]);
                acc2[m][2] = ffma2(pp, vB.x, acc2[m][2]);
                acc2[m][3] = ffma2(pp, vB.y, acc2[m][3]);
            }
        }
    }

    // ---- epilogue: O = acc / l ----
    #pragma unroll
    for (int m = 0; m < 8; m++) {
        float inv = 1.0f / lrow[m];
        u64 inv2 = pack2(inv, inv);
        int i = q0 + tq + 16 * m;
        ulonglong2* dst = (ulonglong2*)(O + ((size_t)b * S + i) * D);
        ulonglong2 o0, o1;
        o0.x = fmul2(acc2[m][0], inv2);
        o0.y = fmul2(acc2[m][1], inv2);
        o1.x = fmul2(acc2[m][2], inv2);
        o1.y = fmul2(acc2[m][3], inv2);
        dst[tk * 2]     = o0;
        dst[tk * 2 + 1] = o1;
    }
}

extern "C" void kernel_launch(void* const* d_in, const int* in_sizes, int n_in,
                              void* d_out, int out_size) {
    const float* q = (const float*)d_in[0];
    const float* k = (const float*)d_in[1];
    const float* v = (const float*)d_in[2];
    float* o = (float*)d_out;

    const int B = 2;
    const int S = in_sizes[0] / (B * D);   // 8192

    size_t smem_bytes = (size_t)SMEM_FLOATS * sizeof(float);  // ~160 KB
    cudaFuncSetAttribute(lminf_kernel, cudaFuncAttributeMaxDynamicSharedMemorySize,
                         (int)smem_bytes);

    dim3 grid(S / TQ, B);
    lminf_kernel<<<grid, NTHREADS, smem_bytes>>>(q, k, v, o, S);
}

// round 3
// speedup vs baseline: 2.0655x; 2.0655x over previous
#include <cuda_runtime.h>
#include <cstdint>

#define D 128
#define TQ 128
#define TK 64
#define NTHREADS 256
#define NGLOBAL 100
#define LPRE 2048

// smem strides chosen so fragment v2 (64-bit) LDS are conflict-free:
// bank-delta = (stride mod 32) * row-delta + col-delta; stride ≡ 8 (mod 32).
#define QS_STRIDE 136
#define KS_STRIDE 136
#define VF_STRIDE 264   // float stride of V pair-packed rows (132 u64)
#define PT_STRIDE 72

#define QS_OFF 0
#define KS_OFF (TQ * QS_STRIDE)                // 17408
#define VF_OFF (KS_OFF + TK * KS_STRIDE)       // 26112 (even -> 8B aligned)
#define PT_OFF (VF_OFF + 32 * VF_STRIDE)       // 34560
#define SMEM_FLOATS (PT_OFF + TQ * PT_STRIDE)  // 43776 floats = 171 KB

typedef unsigned int u32;

__device__ __forceinline__ u32 to_tf32(float x) {
    u32 r;
    asm("cvt.rna.tf32.f32 %0, %1;" : "=r"(r) : "f"(x));
    return r;
}

__device__ __forceinline__ void mma_tf32(float c[4], u32 a0, u32 a1, u32 a2, u32 a3,
                                         u32 b0, u32 b1) {
    asm volatile(
        "mma.sync.aligned.m16n8k8.row.col.f32.tf32.tf32.f32 "
        "{%0,%1,%2,%3}, {%4,%5,%6,%7}, {%8,%9}, {%0,%1,%2,%3};"
        : "+f"(c[0]), "+f"(c[1]), "+f"(c[2]), "+f"(c[3])
        : "r"(a0), "r"(a1), "r"(a2), "r"(a3), "r"(b0), "r"(b1));
}

// column permutation: within each 8-dim group, fragment positions tig and tig+4
// become physically adjacent -> v2 LDS for A/B fragments.
__device__ __forceinline__ int phys_col(int d) {
    return (d & ~7) | ((d & 3) << 1) | ((d >> 2) & 1);
}

// fast exp2 for x <= 0 (poly deg-6, rel err ~1e-5). Handles -1e30 sentinel -> ~0.
__device__ __forceinline__ float fexp2(float x) {
    x = fmaxf(x, -126.0f);
    int ni = __float2int_rd(x);
    float f = x - (float)ni;
    float p = 1.54035304e-4f;
    p = fmaf(p, f, 1.33335581e-3f);
    p = fmaf(p, f, 9.61812911e-3f);
    p = fmaf(p, f, 5.55041087e-2f);
    p = fmaf(p, f, 2.40226507e-1f);
    p = fmaf(p, f, 6.93147181e-1f);
    p = fmaf(p, f, 1.0f);
    return __int_as_float(__float_as_int(p) + (ni << 23));
}

__global__ void __launch_bounds__(NTHREADS, 1)
lminf_kernel(const float* __restrict__ Q, const float* __restrict__ K,
             const float* __restrict__ V, float* __restrict__ O, int S) {
    extern __shared__ float sm[];
    float* Qs = sm + QS_OFF;
    float* Ks = sm + KS_OFF;
    float* Vf = sm + VF_OFF;   // pair-packed: Vf[rv*264 + 2*d + half]
    float* Pt = sm + PT_OFF;

    const int b   = blockIdx.y;
    const int q0  = blockIdx.x * TQ;
    const int tid = threadIdx.x;
    const int w    = tid >> 5;
    const int lane = tid & 31;
    const int g    = lane >> 2;   // group id 0..7
    const int tig  = lane & 3;    // thread-in-group 0..3
    const int qb   = 16 * w;      // warp's q-row base within tile

    const float* Qg = Q + (size_t)b * S * D;
    const float* Kg = K + (size_t)b * S * D;
    const float* Vg = V + (size_t)b * S * D;

    const float QSCALE = 0.0883883476f * 1.44269504089f;  // 1/sqrt(128) * log2(e)
    const float LOG2E  = 1.44269504089f;

    // ---- load Q tile: tf32-rounded, pre-scaled, column-permuted ----
    {
        const float4* src = (const float4*)(Qg + (size_t)q0 * D);
        #pragma unroll
        for (int it = 0; it < (TQ * 32) / NTHREADS; it++) {
            int idx = tid + it * NTHREADS;
            int row = idx >> 5, f4 = idx & 31;
            float4 v = src[idx];
            float vv[4] = {v.x * QSCALE, v.y * QSCALE, v.z * QSCALE, v.w * QSCALE};
            int d0 = f4 * 4;
            #pragma unroll
            for (int e = 0; e < 4; e++)
                Qs[row * QS_STRIDE + phys_col(d0 + e)] = __uint_as_float(to_tf32(vv[e]));
        }
    }

    float co[16][4];              // O accum: 16 dim-tiles x {r0d0,r0d1,r1d0,r1d1}
    #pragma unroll
    for (int nt = 0; nt < 16; nt++)
        #pragma unroll
        for (int e = 0; e < 4; e++) co[nt][e] = 0.0f;
    float m0 = -1e30f, m1 = -1e30f, l0 = 0.0f, l1 = 0.0f;

    const int i0 = q0 + qb + g;
    const int i1 = i0 + 8;

    const int kend = q0 + TQ;
    for (int k0 = 0; k0 < kend; k0 += TK) {
        if (k0 >= NGLOBAL && (k0 + TK) <= (q0 - LPRE + 1)) continue;

        __syncthreads();   // previous tile's PV done reading Vf/Ks
        // ---- load K (permuted) + V (pair-packed) tiles, tf32-rounded ----
        {
            const float4* ksrc = (const float4*)(Kg + (size_t)k0 * D);
            const float4* vsrc = (const float4*)(Vg + (size_t)k0 * D);
            #pragma unroll
            for (int it = 0; it < (TK * 32) / NTHREADS; it++) {
                int idx = tid + it * NTHREADS;
                int row = idx >> 5, f4 = idx & 31;
                int d0 = f4 * 4;
                float4 kv = ksrc[idx];
                float kk4[4] = {kv.x, kv.y, kv.z, kv.w};
                #pragma unroll
                for (int e = 0; e < 4; e++)
                    Ks[row * KS_STRIDE + phys_col(d0 + e)] = __uint_as_float(to_tf32(kk4[e]));
                float4 vv = vsrc[idx];
                float vv4[4] = {vv.x, vv.y, vv.z, vv.w};
                int rv   = 4 * (row >> 3) + (row & 3);
                int half = (row >> 2) & 1;
                #pragma unroll
                for (int e = 0; e < 4; e++)
                    Vf[rv * VF_STRIDE + 2 * (d0 + e) + half] = __uint_as_float(to_tf32(vv4[e]));
            }
        }
        __syncthreads();

        // ---- QK^T: 16x64 per warp via 128 HMMA tf32 ----
        float c[8][4];
        #pragma unroll
        for (int nt = 0; nt < 8; nt++)
            #pragma unroll
            for (int e = 0; e < 4; e++) c[nt][e] = 0.0f;

        #pragma unroll
        for (int kk = 0; kk < 16; kk++) {
            uint2 a02 = *(const uint2*)&Qs[(qb + g)     * QS_STRIDE + 8 * kk + 2 * tig];
            uint2 a13 = *(const uint2*)&Qs[(qb + g + 8) * QS_STRIDE + 8 * kk + 2 * tig];
            #pragma unroll
            for (int nt = 0; nt < 8; nt++) {
                uint2 b01 = *(const uint2*)&Ks[(8 * nt + g) * KS_STRIDE + 8 * kk + 2 * tig];
                mma_tf32(c[nt], a02.x, a13.x, a02.y, a13.y, b01.x, b01.y);
            }
        }

        // ---- mask + bias + online softmax on fragments ----
        float mx0 = -1e30f, mx1 = -1e30f;
        #pragma unroll
        for (int nt = 0; nt < 8; nt++) {
            int j0 = k0 + 8 * nt + 2 * tig;
            int j1 = j0 + 1;
            bool ok00 = (j0 <= i0) && ((j0 < NGLOBAL) || (j0 >= i0 - (LPRE - 1)));
            bool ok01 = (j1 <= i0) && ((j1 < NGLOBAL) || (j1 >= i0 - (LPRE - 1)));
            bool ok10 = (j0 <= i1) && ((j0 < NGLOBAL) || (j0 >= i1 - (LPRE - 1)));
            bool ok11 = (j1 <= i1) && ((j1 < NGLOBAL) || (j1 >= i1 - (LPRE - 1)));
            c[nt][0] = ok00 ? fmaf((float)(j0 - i0), LOG2E, c[nt][0]) : -1e30f;
            c[nt][1] = ok01 ? fmaf((float)(j1 - i0), LOG2E, c[nt][1]) : -1e30f;
            c[nt][2] = ok10 ? fmaf((float)(j0 - i1), LOG2E, c[nt][2]) : -1e30f;
            c[nt][3] = ok11 ? fmaf((float)(j1 - i1), LOG2E, c[nt][3]) : -1e30f;
            mx0 = fmaxf(mx0, fmaxf(c[nt][0], c[nt][1]));
            mx1 = fmaxf(mx1, fmaxf(c[nt][2], c[nt][3]));
        }
        mx0 = fmaxf(mx0, __shfl_xor_sync(0xffffffffu, mx0, 1));
        mx0 = fmaxf(mx0, __shfl_xor_sync(0xffffffffu, mx0, 2));
        mx1 = fmaxf(mx1, __shfl_xor_sync(0xffffffffu, mx1, 1));
        mx1 = fmaxf(mx1, __shfl_xor_sync(0xffffffffu, mx1, 2));

        float mn0 = fmaxf(m0, mx0), mn1 = fmaxf(m1, mx1);
        float sc0 = fexp2(m0 - mn0), sc1 = fexp2(m1 - mn1);
        float ps0 = 0.0f, ps1 = 0.0f;
        #pragma unroll
        for (int nt = 0; nt < 8; nt++) {
            #pragma unroll
            for (int e = 0; e < 2; e++) {
                int jl = 8 * nt + 2 * tig + e;
                int pc = phys_col(jl);
                u32 pb0 = to_tf32(fexp2(c[nt][e]     - mn0));
                u32 pb1 = to_tf32(fexp2(c[nt][2 + e] - mn1));
                ps0 += __uint_as_float(pb0);
                ps1 += __uint_as_float(pb1);
                Pt[(qb + g)     * PT_STRIDE + pc] = __uint_as_float(pb0);
                Pt[(qb + g + 8) * PT_STRIDE + pc] = __uint_as_float(pb1);
            }
        }
        ps0 += __shfl_xor_sync(0xffffffffu, ps0, 1);
        ps0 += __shfl_xor_sync(0xffffffffu, ps0, 2);
        ps1 += __shfl_xor_sync(0xffffffffu, ps1, 1);
        ps1 += __shfl_xor_sync(0xffffffffu, ps1, 2);

        l0 = l0 * sc0 + ps0;  m0 = mn0;
        l1 = l1 * sc1 + ps1;  m1 = mn1;
        #pragma unroll
        for (int nt = 0; nt < 16; nt++) {
            co[nt][0] *= sc0; co[nt][1] *= sc0;
            co[nt][2] *= sc1; co[nt][3] *= sc1;
        }
        __syncwarp();   // P rows are warp-private: warp-level fence suffices

        // ---- P x V: 16x128 per warp via 128 HMMA tf32 ----
        #pragma unroll
        for (int kk2 = 0; kk2 < 8; kk2++) {
            uint2 a02 = *(const uint2*)&Pt[(qb + g)     * PT_STRIDE + 8 * kk2 + 2 * tig];
            uint2 a13 = *(const uint2*)&Pt[(qb + g + 8) * PT_STRIDE + 8 * kk2 + 2 * tig];
            #pragma unroll
            for (int nt = 0; nt < 16; nt++) {
                uint2 b01 = *(const uint2*)&Vf[(4 * kk2 + tig) * VF_STRIDE + 2 * (8 * nt + g)];
                mma_tf32(co[nt], a02.x, a13.x, a02.y, a13.y, b01.x, b01.y);
            }
        }
        __syncwarp();   // PV reads of Pt done before next tile overwrites it
    }

    // ---- epilogue: O = co / l ----
    float inv0 = 1.0f / l0, inv1 = 1.0f / l1;
    float2* o0 = (float2*)(O + ((size_t)b * S + i0) * D);
    float2* o1 = (float2*)(O + ((size_t)b * S + i1) * D);
    #pragma unroll
    for (int nt = 0; nt < 16; nt++) {
        o0[4 * nt + tig] = make_float2(co[nt][0] * inv0, co[nt][1] * inv0);
        o1[4 * nt + tig] = make_float2(co[nt][2] * inv1, co[nt][3] * inv1);
    }
}

extern "C" void kernel_launch(void* const* d_in, const int* in_sizes, int n_in,
                              void* d_out, int out_size) {
    const float* q = (const float*)d_in[0];
    const float* k = (const float*)d_in[1];
    const float* v = (const float*)d_in[2];
    float* o = (float*)d_out;

    const int B = 2;
    const int S = in_sizes[0] / (B * D);   // 8192

    size_t smem_bytes = (size_t)SMEM_FLOATS * sizeof(float);  // ~171 KB
    cudaFuncSetAttribute(lminf_kernel, cudaFuncAttributeMaxDynamicSharedMemorySize,
                         (int)smem_bytes);

    dim3 grid(S / TQ, B);
    lminf_kernel<<<grid, NTHREADS, smem_bytes>>>(q, k, v, o, S);
}